// round 1
// baseline (speedup 1.0000x reference)
#include <cuda_runtime.h>
#include <cuda_bf16.h>

// ---------------------------------------------------------------------------
// 18-qubit statevector fidelity |<psi2|psi1>|^2 for a hardware-efficient
// ansatz: per layer, fused RZ*RY*RX per qubit + CZ chain (diagonal).
//
// State: 2^18 complex64 per circuit (2 MB), kept in __device__ globals,
// fully L2-resident. Per layer: 2 sweeps, each covering 9-10 qubits using
// 32 register-resident amplitudes per thread + warp shuffles. No shared mem.
// ---------------------------------------------------------------------------

#define NQ 18
#define NL 6
#define NSTATE (1 << NQ)

__device__ float2 d_psi[2][NSTATE];          // [state][amp]
__device__ float2 d_mats[2][NL][NQ][4];      // fused 2x2 gate per (state,layer,qubit)
__device__ double d_acc[2];                  // overlap accumulator (re, im)

__device__ __forceinline__ float2 cmul(float2 a, float2 b) {
    return make_float2(a.x * b.x - a.y * b.y, a.x * b.y + a.y * b.x);
}
__device__ __forceinline__ float2 cadd(float2 a, float2 b) {
    return make_float2(a.x + b.x, a.y + b.y);
}
__device__ __forceinline__ float2 rscale(float r, float2 v) {
    return make_float2(r * v.x, r * v.y);
}

// ---------------------------------------------------------------------------
// Prep: compute fused M = RZ(c) * RY(b) * RX(a) for every (state, layer, qubit)
// and zero the overlap accumulators. 216 matrices total.
// ---------------------------------------------------------------------------
__global__ void qk_prep(const float* __restrict__ x1, const float* __restrict__ x2,
                        const float* __restrict__ iscale, const float* __restrict__ var) {
    int t = threadIdx.x;
    if (t < 2) d_acc[t] = 0.0;
    if (t >= 2 * NL * NQ) return;
    int s = t / (NL * NQ);
    int r = t % (NL * NQ);
    int l = r / NQ;
    int q = r % NQ;
    const float* x = s ? x2 : x1;

    float a = iscale[l * NQ + q] * x[q];      // RX angle (data reuploading every layer)
    float b = var[l * 2 * NQ + q];            // RY angle
    float c = var[l * 2 * NQ + NQ + q];       // RZ angle

    float sa, ca, sb, cb, sc, cc;
    sincosf(0.5f * a, &sa, &ca);
    sincosf(0.5f * b, &sb, &cb);
    sincosf(0.5f * c, &sc, &cc);

    // RX = [[(ca,0), (0,-sa)], [(0,-sa), (ca,0)]]
    float2 X00 = make_float2(ca, 0.f), X01 = make_float2(0.f, -sa);
    float2 X10 = make_float2(0.f, -sa), X11 = make_float2(ca, 0.f);
    // M1 = RY @ RX, RY = [[cb,-sb],[sb,cb]]
    float2 M100 = cadd(rscale(cb, X00), rscale(-sb, X10));
    float2 M101 = cadd(rscale(cb, X01), rscale(-sb, X11));
    float2 M110 = cadd(rscale(sb, X00), rscale(cb, X10));
    float2 M111 = cadd(rscale(sb, X01), rscale(cb, X11));
    // M = RZ @ M1, RZ = diag(e^{-ic/2}, e^{+ic/2})
    float2 e0 = make_float2(cc, -sc);
    float2 e1 = make_float2(cc, sc);
    d_mats[s][l][q][0] = cmul(e0, M100);
    d_mats[s][l][q][1] = cmul(e0, M101);
    d_mats[s][l][q][2] = cmul(e1, M110);
    d_mats[s][l][q][3] = cmul(e1, M111);
}

// Apply 2x2 gate between register pair (a, b)
__device__ __forceinline__ void gate_pair(float2& a, float2& b,
                                          float2 m00, float2 m01, float2 m10, float2 m11) {
    float2 na = cadd(cmul(m00, a), cmul(m01, b));
    float2 nb = cadd(cmul(m10, a), cmul(m11, b));
    a = na;
    b = nb;
}

// Apply 2x2 gate along a lane bit via shfl_xor
__device__ __forceinline__ float2 gate_shfl(float2 v, int mask, bool hi,
                                            float2 m00, float2 m01, float2 m10, float2 m11) {
    float2 p;
    p.x = __shfl_xor_sync(0xFFFFFFFFu, v.x, mask);
    p.y = __shfl_xor_sync(0xFFFFFFFFu, v.y, mask);
    float2 x0 = hi ? p : v;
    float2 x1 = hi ? v : p;
    float2 c0 = hi ? m10 : m00;
    float2 c1 = hi ? m11 : m01;
    return cadd(cmul(c0, x0), cmul(c1, x1));
}

// ---------------------------------------------------------------------------
// Sweep A: qubits 0..9. regs = bits 0..4 (32 consecutive amps), lanes = bits 5..9.
// 16384 threads total (2 states x 8192).
// ---------------------------------------------------------------------------
__global__ void __launch_bounds__(128) qk_sweepA(int layer, int init) {
    int t = blockIdx.x * blockDim.x + threadIdx.x;
    int s = t >> 13;
    int lane = t & 31;
    int rest = (t >> 5) & 255;
    unsigned base = ((unsigned)rest << 10) | ((unsigned)lane << 5);
    float2* psi = d_psi[s];

    float2 v[32];
    if (init) {
#pragma unroll
        for (int k = 0; k < 32; k++) v[k] = make_float2(0.f, 0.f);
        if (base == 0) v[0] = make_float2(1.f, 0.f);
    } else {
        const float4* p4 = (const float4*)(psi + base);
#pragma unroll
        for (int k = 0; k < 16; k++) {
            float4 w = p4[k];
            v[2 * k] = make_float2(w.x, w.y);
            v[2 * k + 1] = make_float2(w.z, w.w);
        }
    }

    const float2* M = &d_mats[s][layer][0][0];

    // reg gates: qubits 0..4
#pragma unroll
    for (int q = 0; q < 5; q++) {
        float2 m00 = M[q * 4 + 0], m01 = M[q * 4 + 1], m10 = M[q * 4 + 2], m11 = M[q * 4 + 3];
        int st = 1 << q;
#pragma unroll
        for (int i = 0; i < 32; i++) {
            if ((i & st) == 0) gate_pair(v[i], v[i + st], m00, m01, m10, m11);
        }
    }
    // lane gates: qubits 5..9
#pragma unroll
    for (int q = 5; q < 10; q++) {
        float2 m00 = M[q * 4 + 0], m01 = M[q * 4 + 1], m10 = M[q * 4 + 2], m11 = M[q * 4 + 3];
        int mask = 1 << (q - 5);
        bool hi = (lane & mask) != 0;
#pragma unroll
        for (int k = 0; k < 32; k++) v[k] = gate_shfl(v[k], mask, hi, m00, m01, m10, m11);
    }

    float4* p4 = (float4*)(psi + base);
#pragma unroll
    for (int k = 0; k < 16; k++) {
        p4[k] = make_float4(v[2 * k].x, v[2 * k].y, v[2 * k + 1].x, v[2 * k + 1].y);
    }
}

// ---------------------------------------------------------------------------
// Sweep B: qubits 10..17, plus CZ-chain diagonal sign at the end of the layer.
// regs: k bits -> global bits {0,1} (vectorize), {12}, {16}, {17}
// lanes: lane bits -> global bits {10,11}, {13,14,15}
// rest (8 bits) -> global bits 2..9.
// ---------------------------------------------------------------------------
__global__ void __launch_bounds__(128) qk_sweepB(int layer) {
    int t = blockIdx.x * blockDim.x + threadIdx.x;
    int s = t >> 13;
    int lane = t & 31;
    int rest = (t >> 5) & 255;
    float2* psi = d_psi[s];

    unsigned base2 = ((unsigned)rest << 2) | ((unsigned)(lane & 3) << 10)
                   | ((unsigned)(lane >> 2) << 13);

    float2 v[32];
#pragma unroll
    for (int kk = 0; kk < 8; kk++) {
        unsigned koff = ((unsigned)(kk & 1) << 12) | ((unsigned)((kk >> 1) & 1) << 16)
                      | ((unsigned)(kk >> 2) << 17);
        const float4* p4 = (const float4*)(psi + base2 + koff);
        float4 w0 = p4[0];
        float4 w1 = p4[1];
        v[kk * 4 + 0] = make_float2(w0.x, w0.y);
        v[kk * 4 + 1] = make_float2(w0.z, w0.w);
        v[kk * 4 + 2] = make_float2(w1.x, w1.y);
        v[kk * 4 + 3] = make_float2(w1.z, w1.w);
    }

    const float2* M = &d_mats[s][layer][0][0];

    // qubit -> (is_lane, mask/stride): 10:(L,1) 11:(L,2) 12:(R,4) 13:(L,4) 14:(L,8) 15:(L,16) 16:(R,8) 17:(R,16)
#pragma unroll
    for (int q = 10; q < 18; q++) {
        float2 m00 = M[q * 4 + 0], m01 = M[q * 4 + 1], m10 = M[q * 4 + 2], m11 = M[q * 4 + 3];
        if (q == 12 || q == 16 || q == 17) {
            int st = (q == 12) ? 4 : (q == 16) ? 8 : 16;
#pragma unroll
            for (int i = 0; i < 32; i++) {
                if ((i & st) == 0) gate_pair(v[i], v[i + st], m00, m01, m10, m11);
            }
        } else {
            int mask = (q == 10) ? 1 : (q == 11) ? 2 : (q == 13) ? 4 : (q == 14) ? 8 : 16;
            bool hi = (lane & mask) != 0;
#pragma unroll
            for (int k = 0; k < 32; k++) v[k] = gate_shfl(v[k], mask, hi, m00, m01, m10, m11);
        }
    }

    // CZ chain: sign = (-1)^popc(g & (g>>1) & 0x1FFFF)
#pragma unroll
    for (int k = 0; k < 32; k++) {
        unsigned g = (unsigned)(k & 3) | ((unsigned)rest << 2) | ((unsigned)(lane & 3) << 10)
                   | ((unsigned)((k >> 2) & 1) << 12) | ((unsigned)(lane >> 2) << 13)
                   | ((unsigned)((k >> 3) & 1) << 16) | ((unsigned)((k >> 4) & 1) << 17);
        unsigned tm = g & (g >> 1) & 0x1FFFFu;
        if (__popc(tm) & 1) {
            v[k].x = -v[k].x;
            v[k].y = -v[k].y;
        }
    }

#pragma unroll
    for (int kk = 0; kk < 8; kk++) {
        unsigned koff = ((unsigned)(kk & 1) << 12) | ((unsigned)((kk >> 1) & 1) << 16)
                      | ((unsigned)(kk >> 2) << 17);
        float4* p4 = (float4*)(psi + base2 + koff);
        p4[0] = make_float4(v[kk * 4 + 0].x, v[kk * 4 + 0].y, v[kk * 4 + 1].x, v[kk * 4 + 1].y);
        p4[1] = make_float4(v[kk * 4 + 2].x, v[kk * 4 + 2].y, v[kk * 4 + 3].x, v[kk * 4 + 3].y);
    }
}

// ---------------------------------------------------------------------------
// Overlap reduction: acc += conj(psi2) . psi1 (double accumulation)
// ---------------------------------------------------------------------------
__global__ void qk_reduce() {
    int t = blockIdx.x * blockDim.x + threadIdx.x;
    int nthreads = gridDim.x * blockDim.x;
    double re = 0.0, im = 0.0;
    for (int i = t; i < NSTATE; i += nthreads) {
        float2 a = d_psi[0][i];  // psi1
        float2 b = d_psi[1][i];  // psi2
        re += (double)b.x * a.x + (double)b.y * a.y;
        im += (double)b.x * a.y - (double)b.y * a.x;
    }
#pragma unroll
    for (int o = 16; o > 0; o >>= 1) {
        re += __shfl_down_sync(0xFFFFFFFFu, re, o);
        im += __shfl_down_sync(0xFFFFFFFFu, im, o);
    }
    if ((threadIdx.x & 31) == 0) {
        atomicAdd(&d_acc[0], re);
        atomicAdd(&d_acc[1], im);
    }
}

__global__ void qk_final(float* out) {
    double re = d_acc[0], im = d_acc[1];
    out[0] = (float)(re * re + im * im);
}

extern "C" void kernel_launch(void* const* d_in, const int* in_sizes, int n_in,
                              void* d_out, int out_size) {
    const float* x1 = (const float*)d_in[0];
    const float* x2 = (const float*)d_in[1];
    const float* iscale = (const float*)d_in[2];
    const float* var = (const float*)d_in[3];

    qk_prep<<<1, 256>>>(x1, x2, iscale, var);
    for (int l = 0; l < NL; l++) {
        qk_sweepA<<<128, 128>>>(l, l == 0 ? 1 : 0);
        qk_sweepB<<<128, 128>>>(l);
    }
    qk_reduce<<<128, 256>>>();
    qk_final<<<1, 1>>>((float*)d_out);
}

// round 2
// speedup vs baseline: 1.4195x; 1.4195x over previous
#include <cuda_runtime.h>
#include <cuda_bf16.h>

// ---------------------------------------------------------------------------
// 18-qubit statevector fidelity |<psi2|psi1>|^2, hardware-efficient ansatz.
// Per layer: fused RZ*RY*RX per qubit + CZ-chain (diagonal sign).
//
// R2: 8 amps/thread (64K threads, 2048 warps => ~3.5 warps/SMSP) for latency
// hiding. Pass A covers qubits 0-11 via regs+shfl+one smem transpose
// (XOR-swizzled, bank-conflict-free). Pass B covers 12-17 + CZ sign.
// ---------------------------------------------------------------------------

#define NQ 18
#define NL 6
#define NSTATE (1 << NQ)

__device__ float2 d_psi[2][NSTATE];
__device__ float2 d_mats[2][NL][NQ][4];
__device__ double d_acc[2];

__device__ __forceinline__ float2 cmul(float2 a, float2 b) {
    return make_float2(a.x * b.x - a.y * b.y, a.x * b.y + a.y * b.x);
}
__device__ __forceinline__ float2 cadd(float2 a, float2 b) {
    return make_float2(a.x + b.x, a.y + b.y);
}
__device__ __forceinline__ float2 rscale(float r, float2 v) {
    return make_float2(r * v.x, r * v.y);
}

// ---------------------------------------------------------------------------
// Prep: fused M = RZ(c) * RY(b) * RX(a) for every (state, layer, qubit).
// ---------------------------------------------------------------------------
__global__ void qk_prep(const float* __restrict__ x1, const float* __restrict__ x2,
                        const float* __restrict__ iscale, const float* __restrict__ var) {
    int t = threadIdx.x;
    if (t < 2) d_acc[t] = 0.0;
    if (t >= 2 * NL * NQ) return;
    int s = t / (NL * NQ);
    int r = t % (NL * NQ);
    int l = r / NQ;
    int q = r % NQ;
    const float* x = s ? x2 : x1;

    float a = iscale[l * NQ + q] * x[q];
    float b = var[l * 2 * NQ + q];
    float c = var[l * 2 * NQ + NQ + q];

    float sa, ca, sb, cb, sc, cc;
    sincosf(0.5f * a, &sa, &ca);
    sincosf(0.5f * b, &sb, &cb);
    sincosf(0.5f * c, &sc, &cc);

    float2 X00 = make_float2(ca, 0.f), X01 = make_float2(0.f, -sa);
    float2 X10 = make_float2(0.f, -sa), X11 = make_float2(ca, 0.f);
    float2 M100 = cadd(rscale(cb, X00), rscale(-sb, X10));
    float2 M101 = cadd(rscale(cb, X01), rscale(-sb, X11));
    float2 M110 = cadd(rscale(sb, X00), rscale(cb, X10));
    float2 M111 = cadd(rscale(sb, X01), rscale(cb, X11));
    float2 e0 = make_float2(cc, -sc);
    float2 e1 = make_float2(cc, sc);
    d_mats[s][l][q][0] = cmul(e0, M100);
    d_mats[s][l][q][1] = cmul(e0, M101);
    d_mats[s][l][q][2] = cmul(e1, M110);
    d_mats[s][l][q][3] = cmul(e1, M111);
}

__device__ __forceinline__ void gate_pair(float2& a, float2& b,
                                          float2 m00, float2 m01, float2 m10, float2 m11) {
    float2 na = cadd(cmul(m00, a), cmul(m01, b));
    float2 nb = cadd(cmul(m10, a), cmul(m11, b));
    a = na;
    b = nb;
}

__device__ __forceinline__ float2 gate_shfl(float2 v, int mask, bool hi,
                                            float2 m00, float2 m01, float2 m10, float2 m11) {
    float2 p;
    p.x = __shfl_xor_sync(0xFFFFFFFFu, v.x, mask);
    p.y = __shfl_xor_sync(0xFFFFFFFFu, v.y, mask);
    float2 x0 = hi ? p : v;
    float2 x1 = hi ? v : p;
    float2 c0 = hi ? m10 : m00;
    float2 c1 = hi ? m11 : m01;
    return cadd(cmul(c0, x0), cmul(c1, x1));
}

// smem swizzle: conflict-free for all three access patterns used in pass A
__device__ __forceinline__ unsigned swz(unsigned amp) {
    return amp ^ ((amp >> 4) & 15u);
}

// ---------------------------------------------------------------------------
// Pass A: qubits 0..11. Block = 512 threads, 4096 amps (local bits 0-11).
// Mapping 1: k = bits 0-2 (8 consecutive amps), lane = bits 3-7, w = bits 8-11.
//   reg gates q0-2, shfl gates q3-7. Then STS (swizzled).
// Mapping 2: k' = bits 9-11, lane' = bits {0-3, 8}, w' = bits 4-7.
//   shfl gate q8 (mask 16), reg gates q9-11. STG coalesced.
// ---------------------------------------------------------------------------
__global__ void __launch_bounds__(512) qk_passA(int layer, int init) {
    __shared__ float2 sm[4096];
    int tid = threadIdx.x;
    int s = blockIdx.x >> 6;
    unsigned blkbase = ((unsigned)(blockIdx.x & 63)) << 12;
    int lane = tid & 31;
    int w = tid >> 5;                       // 0..15
    float2* psi = d_psi[s];
    const float2* M = &d_mats[s][layer][0][0];

    unsigned base1 = ((unsigned)w << 8) | ((unsigned)lane << 3);  // local amp base
    float2 v[8];

    if (init) {
#pragma unroll
        for (int k = 0; k < 8; k++) v[k] = make_float2(0.f, 0.f);
        if (blkbase + base1 == 0) v[0] = make_float2(1.f, 0.f);
    } else {
        const float4* p4 = (const float4*)(psi + blkbase + base1);
#pragma unroll
        for (int j = 0; j < 4; j++) {
            float4 t4 = p4[j];
            v[2 * j] = make_float2(t4.x, t4.y);
            v[2 * j + 1] = make_float2(t4.z, t4.w);
        }
    }

    // reg gates: qubits 0..2
#pragma unroll
    for (int q = 0; q < 3; q++) {
        float2 m00 = M[q * 4 + 0], m01 = M[q * 4 + 1], m10 = M[q * 4 + 2], m11 = M[q * 4 + 3];
        int st = 1 << q;
#pragma unroll
        for (int i = 0; i < 8; i++)
            if ((i & st) == 0) gate_pair(v[i], v[i + st], m00, m01, m10, m11);
    }
    // lane gates: qubits 3..7
#pragma unroll
    for (int q = 3; q < 8; q++) {
        float2 m00 = M[q * 4 + 0], m01 = M[q * 4 + 1], m10 = M[q * 4 + 2], m11 = M[q * 4 + 3];
        int mask = 1 << (q - 3);
        bool hi = (lane & mask) != 0;
#pragma unroll
        for (int k = 0; k < 8; k++) v[k] = gate_shfl(v[k], mask, hi, m00, m01, m10, m11);
    }

    // store to smem (swizzled)
#pragma unroll
    for (int k = 0; k < 8; k++) sm[swz(base1 | k)] = v[k];
    __syncthreads();

    // Mapping 2: k' = bits 9-11, lane' bits -> amp {0,1,2,3, 8}, w' = bits 4-7
    int lp = lane;                          // lane'
    int wp = w;                             // w'
    unsigned base2 = ((unsigned)(lp & 15)) | ((unsigned)(lp >> 4) << 8) | ((unsigned)wp << 4);
#pragma unroll
    for (int k = 0; k < 8; k++) v[k] = sm[swz(base2 | ((unsigned)k << 9))];

    // shfl gate q8 (lane' bit 4)
    {
        float2 m00 = M[8 * 4 + 0], m01 = M[8 * 4 + 1], m10 = M[8 * 4 + 2], m11 = M[8 * 4 + 3];
        bool hi = (lp & 16) != 0;
#pragma unroll
        for (int k = 0; k < 8; k++) v[k] = gate_shfl(v[k], 16, hi, m00, m01, m10, m11);
    }
    // reg gates q9,10,11 (k' strides 1,2,4)
#pragma unroll
    for (int q = 9; q < 12; q++) {
        float2 m00 = M[q * 4 + 0], m01 = M[q * 4 + 1], m10 = M[q * 4 + 2], m11 = M[q * 4 + 3];
        int st = 1 << (q - 9);
#pragma unroll
        for (int i = 0; i < 8; i++)
            if ((i & st) == 0) gate_pair(v[i], v[i + st], m00, m01, m10, m11);
    }

    // store to global: per k', 32 lanes cover two contiguous 128B runs
#pragma unroll
    for (int k = 0; k < 8; k++)
        psi[blkbase + base2 + ((unsigned)k << 9)] = v[k];
}

// ---------------------------------------------------------------------------
// Pass B: qubits 12..17 + CZ-chain sign. 8 amps/thread.
// regs k: bits {0,1,12}; lanes: bits 13-17; rest: bits 2-11.
// ---------------------------------------------------------------------------
__global__ void __launch_bounds__(256) qk_passB(int layer) {
    int t = blockIdx.x * 256 + threadIdx.x;
    int s = t >> 15;
    int r = t & 32767;
    int lane = r & 31;
    unsigned rest = (unsigned)(r >> 5);     // 10 bits -> amp bits 2-11
    unsigned base = (rest << 2) | ((unsigned)lane << 13);
    float2* psi = d_psi[s];
    const float2* M = &d_mats[s][layer][0][0];

    float2 v[8];
#pragma unroll
    for (int kk = 0; kk < 2; kk++) {
        unsigned off = ((unsigned)kk << 12);
        const float4* p4 = (const float4*)(psi + base + off);
        float4 w0 = p4[0];
        float4 w1 = p4[1];
        v[kk * 4 + 0] = make_float2(w0.x, w0.y);
        v[kk * 4 + 1] = make_float2(w0.z, w0.w);
        v[kk * 4 + 2] = make_float2(w1.x, w1.y);
        v[kk * 4 + 3] = make_float2(w1.z, w1.w);
    }

    // reg gate q12: k bit 2 (stride 4)
    {
        float2 m00 = M[12 * 4 + 0], m01 = M[12 * 4 + 1], m10 = M[12 * 4 + 2], m11 = M[12 * 4 + 3];
#pragma unroll
        for (int i = 0; i < 4; i++) gate_pair(v[i], v[i + 4], m00, m01, m10, m11);
    }
    // lane gates q13..17 (masks 1,2,4,8,16)
#pragma unroll
    for (int q = 13; q < 18; q++) {
        float2 m00 = M[q * 4 + 0], m01 = M[q * 4 + 1], m10 = M[q * 4 + 2], m11 = M[q * 4 + 3];
        int mask = 1 << (q - 13);
        bool hi = (lane & mask) != 0;
#pragma unroll
        for (int k = 0; k < 8; k++) v[k] = gate_shfl(v[k], mask, hi, m00, m01, m10, m11);
    }

    // CZ chain sign: (-1)^popc(g & (g>>1) & 0x1FFFF)
#pragma unroll
    for (int k = 0; k < 8; k++) {
        unsigned g = base | (unsigned)(k & 3) | ((unsigned)(k >> 2) << 12);
        unsigned tm = g & (g >> 1) & 0x1FFFFu;
        if (__popc(tm) & 1) {
            v[k].x = -v[k].x;
            v[k].y = -v[k].y;
        }
    }

#pragma unroll
    for (int kk = 0; kk < 2; kk++) {
        unsigned off = ((unsigned)kk << 12);
        float4* p4 = (float4*)(psi + base + off);
        p4[0] = make_float4(v[kk * 4 + 0].x, v[kk * 4 + 0].y, v[kk * 4 + 1].x, v[kk * 4 + 1].y);
        p4[1] = make_float4(v[kk * 4 + 2].x, v[kk * 4 + 2].y, v[kk * 4 + 3].x, v[kk * 4 + 3].y);
    }
}

// ---------------------------------------------------------------------------
// Overlap reduction: acc += conj(psi2) . psi1
// ---------------------------------------------------------------------------
__global__ void qk_reduce() {
    int t = blockIdx.x * blockDim.x + threadIdx.x;
    int nthreads = gridDim.x * blockDim.x;
    double re = 0.0, im = 0.0;
    for (int i = t; i < NSTATE; i += nthreads) {
        float2 a = d_psi[0][i];
        float2 b = d_psi[1][i];
        re += (double)b.x * a.x + (double)b.y * a.y;
        im += (double)b.x * a.y - (double)b.y * a.x;
    }
#pragma unroll
    for (int o = 16; o > 0; o >>= 1) {
        re += __shfl_down_sync(0xFFFFFFFFu, re, o);
        im += __shfl_down_sync(0xFFFFFFFFu, im, o);
    }
    if ((threadIdx.x & 31) == 0) {
        atomicAdd(&d_acc[0], re);
        atomicAdd(&d_acc[1], im);
    }
}

__global__ void qk_final(float* out) {
    double re = d_acc[0], im = d_acc[1];
    out[0] = (float)(re * re + im * im);
}

extern "C" void kernel_launch(void* const* d_in, const int* in_sizes, int n_in,
                              void* d_out, int out_size) {
    const float* x1 = (const float*)d_in[0];
    const float* x2 = (const float*)d_in[1];
    const float* iscale = (const float*)d_in[2];
    const float* var = (const float*)d_in[3];

    qk_prep<<<1, 256>>>(x1, x2, iscale, var);
    for (int l = 0; l < NL; l++) {
        qk_passA<<<128, 512>>>(l, l == 0 ? 1 : 0);
        qk_passB<<<256, 256>>>(l);
    }
    qk_reduce<<<128, 256>>>();
    qk_final<<<1, 1>>>((float*)d_out);
}